// round 7
// baseline (speedup 1.0000x reference)
#include <cuda_runtime.h>
#include <cuda_bf16.h>
#include <cstdint>
#include <math_constants.h>

#define BATCH 32
#define SLEN  2048
#define DDIM  128
#define HDIM  256
#define KCODE 512

// ---------------- scratch (static device globals; no allocation) ----------------
__device__ float g_h1 [(size_t)BATCH * HDIM * SLEN];   // 64 MB  enc1 out, channel-first
__device__ float g_h2 [(size_t)BATCH * HDIM * SLEN];   // 64 MB  enc2 out, channel-first
__device__ float g_z  [(size_t)BATCH * DDIM * SLEN];   // 32 MB  enc3 out, channel-first
__device__ float g_zqh[(size_t)BATCH * SLEN * DDIM];   // 32 MB  z_q split hi, channel-last
__device__ float g_zql[(size_t)BATCH * SLEN * DDIM];   // 32 MB  z_q split lo
__device__ float g_d1h[(size_t)BATCH * SLEN * HDIM];   // 64 MB  dec1 out split hi
__device__ float g_d1l[(size_t)BATCH * SLEN * HDIM];   // 64 MB  dec1 out split lo
__device__ float g_d2 [(size_t)BATCH * SLEN * HDIM];   // 64 MB  dec2 out fp32, channel-last
__device__ float g_wh[HDIM * 3 * HDIM];                // K-major weight hi (tf32)
__device__ float g_wl[HDIM * 3 * HDIM];                // K-major weight lo (tf32)
__device__ float g_c2[KCODE];
__device__ double g_acc[2];                             // [0]=sum min dist, [1]=recon SSE

// ---------------- helpers ----------------
__device__ __forceinline__ float tf32_rna(float v) {
    uint32_t o;
    asm("cvt.rna.tf32.f32 %0, %1;" : "=r"(o) : "f"(v));
    return __uint_as_float(o);
}

__device__ __forceinline__ void mma1688_tf32(float* d, const float* a, const float* b) {
    asm volatile(
        "mma.sync.aligned.m16n8k8.row.col.f32.tf32.tf32.f32 "
        "{%0,%1,%2,%3}, {%4,%5,%6,%7}, {%8,%9}, {%0,%1,%2,%3};"
        : "+f"(d[0]), "+f"(d[1]), "+f"(d[2]), "+f"(d[3])
        : "r"(__float_as_uint(a[0])), "r"(__float_as_uint(a[1])),
          "r"(__float_as_uint(a[2])), "r"(__float_as_uint(a[3])),
          "r"(__float_as_uint(b[0])), "r"(__float_as_uint(b[1])));
}

// ---------------- init ----------------
__global__ void init_k() {
    if (threadIdx.x < 2) g_acc[threadIdx.x] = 0.0;
}

// ---------------- codebook norms ----------------
__global__ void c2_k(const float* __restrict__ cb) {
    int k = blockIdx.x * blockDim.x + threadIdx.x;
    if (k < KCODE) {
        const float* r = cb + (size_t)k * DDIM;
        float s = 0.f;
        #pragma unroll 8
        for (int d = 0; d < DDIM; d++) s += r[d] * r[d];
        g_c2[k] = s;
    }
}

// ---------------- encoder conv1: 1 -> H, k=3, SAME, lrelu (round-1 proven) ---
__global__ __launch_bounds__(256) void enc1_k(const float* __restrict__ x,
                                              const float* __restrict__ w,
                                              const float* __restrict__ bias) {
    size_t idx = (size_t)blockIdx.x * blockDim.x + threadIdx.x;   // over B*H*S
    int s = idx & (SLEN - 1);
    int c = (idx >> 11) & (HDIM - 1);
    int b = idx >> 19;
    const float* xb = x + (size_t)b * SLEN;
    float v = bias[c];
    float w0 = w[c*3+0], w1 = w[c*3+1], w2 = w[c*3+2];
    if (s > 0)        v += w0 * xb[s-1];
    v += w1 * xb[s];
    if (s < SLEN - 1) v += w2 * xb[s+1];
    g_h1[idx] = (v >= 0.f) ? v : 0.2f * v;
}

// ------------ SIMT fp32 conv (round-1 proven): channel-first ------------
template<int CI, int CO, bool RELU>
__global__ __launch_bounds__(256) void conv_k(const float* __restrict__ in,
                                              const float* __restrict__ w,
                                              const float* __restrict__ bias,
                                              float* __restrict__ out) {
    const int s_tile  = blockIdx.x * 64;
    const int co_base = blockIdx.y * 128;
    const int b       = blockIdx.z;
    const int tid = threadIdx.x;
    const int tx  = tid & 15;    // s group   (4 outputs)
    const int ty  = tid >> 4;    // co group  (8 outputs)

    __shared__ float ws[48 * 130];       // [ci*3+t][co], stride 130
    __shared__ float ins[16][72];        // [ci][sp], sp in 0..65

    float acc[8][4];
    #pragma unroll
    for (int v = 0; v < 8; v++)
        #pragma unroll
        for (int u = 0; u < 4; u++) acc[v][u] = 0.f;

    const float* in_b = in + (size_t)b * CI * SLEN;

    for (int ci0 = 0; ci0 < CI; ci0 += 16) {
        __syncthreads();
        for (int i = tid; i < 16 * 66; i += 256) {
            int ci = i / 66, sp = i - ci * 66;
            int s = s_tile - 1 + sp;
            float v = 0.f;
            if (s >= 0 && s < SLEN) v = in_b[(size_t)(ci0 + ci) * SLEN + s];
            ins[ci][sp] = v;
        }
        for (int i = tid; i < 128 * 48; i += 256) {
            int co = i / 48, j = i - co * 48;            // j = ci_local*3 + t
            ws[j * 130 + co] = w[(size_t)(co_base + co) * (CI * 3) + (size_t)ci0 * 3 + j];
        }
        __syncthreads();

        #pragma unroll
        for (int ci = 0; ci < 16; ci++) {
            float xv[6];
            #pragma unroll
            for (int u = 0; u < 6; u++) xv[u] = ins[ci][tx * 4 + u];
            #pragma unroll
            for (int t = 0; t < 3; t++) {
                float wv[8];
                #pragma unroll
                for (int v = 0; v < 8; v++) wv[v] = ws[(ci * 3 + t) * 130 + ty * 8 + v];
                #pragma unroll
                for (int v = 0; v < 8; v++)
                    #pragma unroll
                    for (int u = 0; u < 4; u++)
                        acc[v][u] += wv[v] * xv[u + t];
            }
        }
    }

    #pragma unroll
    for (int v = 0; v < 8; v++) {
        int co = co_base + ty * 8 + v;
        float bb = bias[co];
        #pragma unroll
        for (int u = 0; u < 4; u++) {
            int s = s_tile + tx * 4 + u;
            float r = acc[v][u] + bb;
            if (RELU) r = (r >= 0.f) ? r : 0.2f * r;
            out[((size_t)b * CO + co) * SLEN + s] = r;
        }
    }
}

// ------- VQ (round-5 verbatim arithmetic); z_q stored SPLIT channel-last -------
__global__ __launch_bounds__(256) void vq_k(const float* __restrict__ cb,
                                            float* __restrict__ out_idx) {
    int gp = blockIdx.x * 256 + threadIdx.x;     // global position in [0, B*S)
    int b = gp >> 11;
    int s = gp & (SLEN - 1);

    const float* zb = g_z + (size_t)b * DDIM * SLEN + s;
    float zr[DDIM];
    #pragma unroll
    for (int d = 0; d < DDIM; d++) zr[d] = zb[(size_t)d * SLEN];

    float z2 = 0.f;
    #pragma unroll
    for (int d = 0; d < DDIM; d++) z2 += zr[d] * zr[d];

    float best = CUDART_INF_F;
    int bi = 0;
    const float4* cb4 = reinterpret_cast<const float4*>(cb);
    for (int k = 0; k < KCODE; k++) {
        float d0 = 0.f, d1 = 0.f, d2 = 0.f, d3 = 0.f;
        #pragma unroll
        for (int q = 0; q < 32; q++) {
            float4 c = __ldg(&cb4[k * 32 + q]);
            d0 += c.x * zr[4*q+0];
            d1 += c.y * zr[4*q+1];
            d2 += c.z * zr[4*q+2];
            d3 += c.w * zr[4*q+3];
        }
        float dist = z2 + __ldg(&g_c2[k]) - 2.f * ((d0 + d1) + (d2 + d3));
        if (dist < best) { best = dist; bi = k; }
    }

    out_idx[gp] = (float)bi;

    const float* cc = cb + (size_t)bi * DDIM;
    float qs = 0.f;
    #pragma unroll
    for (int d = 0; d < DDIM; d++) {
        float df = zr[d] - cc[d];
        qs += df * df;
    }
    // store z_q pre-split (identical tf32 values round-5's dec1 computed in-loop)
    float4* zqh = reinterpret_cast<float4*>(g_zqh + (size_t)gp * DDIM);
    float4* zql = reinterpret_cast<float4*>(g_zql + (size_t)gp * DDIM);
    #pragma unroll
    for (int q = 0; q < 32; q++) {
        float4 c = __ldg(reinterpret_cast<const float4*>(cc) + q);
        float4 h, l;
        h.x = tf32_rna(c.x); l.x = tf32_rna(c.x - h.x);
        h.y = tf32_rna(c.y); l.y = tf32_rna(c.y - h.y);
        h.z = tf32_rna(c.z); l.z = tf32_rna(c.z - h.z);
        h.w = tf32_rna(c.w); l.w = tf32_rna(c.w - h.w);
        zqh[q] = h;
        zql[q] = l;
    }

    __shared__ float red[256];
    red[threadIdx.x] = qs;
    __syncthreads();
    for (int off = 128; off > 0; off >>= 1) {
        if (threadIdx.x < off) red[threadIdx.x] += red[threadIdx.x + off];
        __syncthreads();
    }
    if (threadIdx.x == 0) atomicAdd(&g_acc[0], (double)red[0]);
}

// weight prep: [CO][ci*3+t] fp32 -> K-major [CO][t*CI+ci] tf32 hi/lo
template<int CO, int CI>
__global__ __launch_bounds__(256) void wprep_k(const float* __restrict__ w,
                                               float* __restrict__ wh,
                                               float* __restrict__ wl) {
    int idx = blockIdx.x * 256 + threadIdx.x;        // over CO*3*CI
    int co = idx / (3 * CI);
    int r  = idx - co * (3 * CI);                    // = t*CI + ci
    int t  = r / CI;
    int ci = r - t * CI;
    float v = w[(size_t)co * 3 * CI + (size_t)ci * 3 + t];
    float h = tf32_rna(v);
    wh[idx] = h;
    wl[idx] = tf32_rna(v - h);
}

// ============ 3xTF32 HMMA conv (pre-split inputs): CI -> CO, k=3 SAME ============
// OMODE: 0 = fp32 channel-last; 1 = split hi/lo channel-last.
template<int CI, int CO, bool RELU, int OMODE>
__global__ __launch_bounds__(256, 2) void conv_mma_k(const float* __restrict__ inh,
                                                     const float* __restrict__ inl,
                                                     const float* __restrict__ wh,
                                                     const float* __restrict__ wl,
                                                     const float* __restrict__ bias,
                                                     float* __restrict__ o1,
                                                     float* __restrict__ o2) {
    constexpr int KTOT = 3 * CI;
    constexpr int NCH  = KTOT / 32;
    constexpr int RSTR = 36;                 // floats per smem row (32 + 4 pad)

    extern __shared__ float sm[];
    float* Ah = sm;
    float* Al = sm + 128 * RSTR;
    float* Bh = sm + 2 * 128 * RSTR;
    float* Bl = sm + 3 * 128 * RSTR;

    const int tid  = threadIdx.x;
    const int lane = tid & 31;
    const int wid  = tid >> 5;
    const int wm   = wid & 1;                // 2 warps over co
    const int wn   = wid >> 1;               // 4 warps over p
    const int g    = lane >> 2;              // group id 0..7
    const int t4   = lane & 3;               // thread-in-group 0..3

    const int bs_base = blockIdx.x * 128;
    const int co_base = blockIdx.y * 128;
    const int s_in_b0 = bs_base & (SLEN - 1);

    float acc[4][4][4];
    #pragma unroll
    for (int i = 0; i < 4; i++)
        #pragma unroll
        for (int j = 0; j < 4; j++)
            #pragma unroll
            for (int e = 0; e < 4; e++) acc[i][j][e] = 0.f;

    for (int kc = 0; kc < NCH; kc++) {
        const int t   = (kc * 32) / CI;       // tap (chunk never crosses taps; CI%32==0)
        const int ci0 = (kc * 32) % CI;
        __syncthreads();

        // ---- A tile: 128co x 32k (pre-split tf32 weights, coalesced) ----
        #pragma unroll
        for (int j = 0; j < 4; j++) {
            int idx = tid + 256 * j;          // 1024 float4
            int row = idx >> 3, q = idx & 7;
            size_t src = (size_t)(co_base + row) * KTOT + kc * 32 + 4 * q;
            float4 vh = *reinterpret_cast<const float4*>(wh + src);
            float4 vl = *reinterpret_cast<const float4*>(wl + src);
            *reinterpret_cast<float4*>(Ah + row * RSTR + 4 * q) = vh;
            *reinterpret_cast<float4*>(Al + row * RSTR + 4 * q) = vl;
        }
        // ---- B tile: 128p x 32k (pre-split activations, pure copies) ----
        #pragma unroll
        for (int j = 0; j < 4; j++) {
            int idx = tid + 256 * j;          // 1024 float4
            int row = idx >> 3, q = idx & 7;
            int sb = s_in_b0 + row + t - 1;
            float4 vh = make_float4(0.f, 0.f, 0.f, 0.f);
            float4 vl = make_float4(0.f, 0.f, 0.f, 0.f);
            if (sb >= 0 && sb < SLEN) {
                size_t src = (size_t)(bs_base + row + t - 1) * CI + ci0 + 4 * q;
                vh = *reinterpret_cast<const float4*>(inh + src);
                vl = *reinterpret_cast<const float4*>(inl + src);
            }
            *reinterpret_cast<float4*>(Bh + row * RSTR + 4 * q) = vh;
            *reinterpret_cast<float4*>(Bl + row * RSTR + 4 * q) = vl;
        }
        __syncthreads();

        #pragma unroll
        for (int ks = 0; ks < 4; ks++) {
            const int k0 = ks * 8 + t4;       // this thread's k column
            float bhf[4][2], blf[4][2];
            #pragma unroll
            for (int nf = 0; nf < 4; nf++) {
                int nrow = wn * 32 + nf * 8 + g;
                bhf[nf][0] = Bh[nrow * RSTR + k0];
                bhf[nf][1] = Bh[nrow * RSTR + k0 + 4];
                blf[nf][0] = Bl[nrow * RSTR + k0];
                blf[nf][1] = Bl[nrow * RSTR + k0 + 4];
            }
            #pragma unroll
            for (int mf = 0; mf < 4; mf++) {
                int mrow = wm * 64 + mf * 16 + g;
                float ahf[4], alf[4];
                ahf[0] = Ah[mrow * RSTR + k0];
                ahf[1] = Ah[(mrow + 8) * RSTR + k0];
                ahf[2] = Ah[mrow * RSTR + k0 + 4];
                ahf[3] = Ah[(mrow + 8) * RSTR + k0 + 4];
                alf[0] = Al[mrow * RSTR + k0];
                alf[1] = Al[(mrow + 8) * RSTR + k0];
                alf[2] = Al[mrow * RSTR + k0 + 4];
                alf[3] = Al[(mrow + 8) * RSTR + k0 + 4];
                #pragma unroll
                for (int nf = 0; nf < 4; nf++) {
                    mma1688_tf32(acc[mf][nf], ahf, bhf[nf]);
                    mma1688_tf32(acc[mf][nf], ahf, blf[nf]);
                    mma1688_tf32(acc[mf][nf], alf, bhf[nf]);
                }
            }
        }
    }

    // ---- epilogue: bias + lrelu (+ optional split) + channel-last store ----
    #pragma unroll
    for (int mf = 0; mf < 4; mf++) {
        int co0 = co_base + wm * 64 + mf * 16 + g;
        float bb0 = bias[co0];
        float bb1 = bias[co0 + 8];
        #pragma unroll
        for (int nf = 0; nf < 4; nf++) {
            int p = bs_base + wn * 32 + nf * 8 + t4 * 2;
            #pragma unroll
            for (int e = 0; e < 2; e++) {
                float v0 = acc[mf][nf][e] + bb0;       // row g,   col t4*2+e
                float v1 = acc[mf][nf][2 + e] + bb1;   // row g+8, col t4*2+e
                if (RELU) {
                    v0 = (v0 >= 0.f) ? v0 : 0.2f * v0;
                    v1 = (v1 >= 0.f) ? v1 : 0.2f * v1;
                }
                int pp = p + e;
                if (OMODE == 0) {
                    o1[(size_t)pp * CO + co0]     = v0;
                    o1[(size_t)pp * CO + co0 + 8] = v1;
                } else {
                    float h0 = tf32_rna(v0), h1 = tf32_rna(v1);
                    o1[(size_t)pp * CO + co0]     = h0;
                    o1[(size_t)pp * CO + co0 + 8] = h1;
                    o2[(size_t)pp * CO + co0]     = tf32_rna(v0 - h0);
                    o2[(size_t)pp * CO + co0 + 8] = tf32_rna(v1 - h1);
                }
            }
        }
    }
}

// ---------------- decoder conv3: H -> 1 (channel-last input) + recon loss ----
__global__ __launch_bounds__(256) void dec3_k(const float* __restrict__ hin,
                                              const float* __restrict__ w,
                                              const float* __restrict__ bias,
                                              const float* __restrict__ x,
                                              float* __restrict__ xrec) {
    __shared__ float ws[HDIM * 3];
    for (int i = threadIdx.x; i < HDIM * 3; i += 256) ws[i] = w[i];
    __syncthreads();

    int wid = threadIdx.x >> 5, lane = threadIdx.x & 31;
    int p = blockIdx.x * 8 + wid;     // global position
    int s = p & (SLEN - 1);

    float acc = 0.f;
    #pragma unroll
    for (int t = 0; t < 3; t++) {
        int sb = s + t - 1;
        if (sb < 0 || sb >= SLEN) continue;
        const float4* r = reinterpret_cast<const float4*>(hin + (size_t)(p + t - 1) * HDIM);
        #pragma unroll
        for (int q = 0; q < 2; q++) {
            float4 v = r[lane * 2 + q];
            int c0 = lane * 8 + q * 4;
            acc += v.x * ws[(c0+0)*3+t] + v.y * ws[(c0+1)*3+t]
                 + v.z * ws[(c0+2)*3+t] + v.w * ws[(c0+3)*3+t];
        }
    }
    #pragma unroll
    for (int off = 16; off > 0; off >>= 1)
        acc += __shfl_xor_sync(0xFFFFFFFFu, acc, off);

    __shared__ float wsum[8];
    if (lane == 0) {
        float a = acc + bias[0];
        xrec[p] = a;
        float diff = x[p] - a;
        wsum[wid] = diff * diff;
    }
    __syncthreads();
    if (threadIdx.x == 0) {
        float s8 = 0.f;
        #pragma unroll
        for (int i = 0; i < 8; i++) s8 += wsum[i];
        atomicAdd(&g_acc[1], (double)s8);
    }
}

// ---------------- finalize losses ----------------
__global__ void fin_k(float* __restrict__ out) {
    double qsum = g_acc[0];
    double rsum = g_acc[1];
    float qm    = (float)(qsum / ((double)BATCH * SLEN * DDIM));
    float recon = (float)(rsum / ((double)BATCH * SLEN));
    float vq    = qm * 0.05f;
    float com   = qm * 0.15f;
    size_t base = (size_t)2 * BATCH * SLEN;
    out[base + 0] = recon + vq + com;
    out[base + 1] = recon;
    out[base + 2] = vq;
    out[base + 3] = com;
}

// ---------------- launch ----------------
static const int CONV_SMEM = 4 * 128 * 36 * 4;   // 73728 bytes

extern "C" void kernel_launch(void* const* d_in, const int* in_sizes, int n_in,
                              void* d_out, int out_size) {
    const float* x   = (const float*)d_in[0];
    const float* cb  = (const float*)d_in[1];
    const float* ew1 = (const float*)d_in[2];
    const float* eb1 = (const float*)d_in[3];
    const float* ew2 = (const float*)d_in[4];
    const float* eb2 = (const float*)d_in[5];
    const float* ew3 = (const float*)d_in[6];
    const float* eb3 = (const float*)d_in[7];
    const float* dw1 = (const float*)d_in[8];
    const float* db1 = (const float*)d_in[9];
    const float* dw2 = (const float*)d_in[10];
    const float* db2 = (const float*)d_in[11];
    const float* dw3 = (const float*)d_in[12];
    const float* db3 = (const float*)d_in[13];
    float* out = (float*)d_out;

    float *h1, *h2, *z, *zqh, *zql, *d1h, *d1l, *d2, *wh, *wl;
    cudaGetSymbolAddress((void**)&h1,  g_h1);
    cudaGetSymbolAddress((void**)&h2,  g_h2);
    cudaGetSymbolAddress((void**)&z,   g_z);
    cudaGetSymbolAddress((void**)&zqh, g_zqh);
    cudaGetSymbolAddress((void**)&zql, g_zql);
    cudaGetSymbolAddress((void**)&d1h, g_d1h);
    cudaGetSymbolAddress((void**)&d1l, g_d1l);
    cudaGetSymbolAddress((void**)&d2,  g_d2);
    cudaGetSymbolAddress((void**)&wh,  g_wh);
    cudaGetSymbolAddress((void**)&wl,  g_wl);

    cudaFuncSetAttribute(conv_mma_k<DDIM, HDIM, true, 1>,
                         cudaFuncAttributeMaxDynamicSharedMemorySize, CONV_SMEM);
    cudaFuncSetAttribute(conv_mma_k<HDIM, HDIM, true, 0>,
                         cudaFuncAttributeMaxDynamicSharedMemorySize, CONV_SMEM);

    init_k<<<1, 32>>>();
    c2_k<<<2, 256>>>(cb);

    // ---------- encoder: round-5 proven fp32 path (channel-first) ----------
    enc1_k<<<(BATCH * HDIM * SLEN) / 256, 256>>>(x, ew1, eb1);

    dim3 g2(SLEN / 64, HDIM / 128, BATCH);
    conv_k<HDIM, HDIM, true><<<g2, 256>>>(h1, ew2, eb2, h2);

    dim3 g3(SLEN / 64, DDIM / 128, BATCH);
    conv_k<HDIM, DDIM, false><<<g3, 256>>>(h2, ew3, eb3, z);

    // ---------- VQ: round-5 verbatim arithmetic; z_q written split ----------
    vq_k<<<(BATCH * SLEN) / 256, 256>>>(cb, out + (size_t)BATCH * SLEN);

    // ---------- decoder: 3xTF32 MMA, pre-split operands (values == round 5) ----------
    const int STILES = (BATCH * SLEN) / 128;   // 512

    wprep_k<HDIM, DDIM><<<(HDIM * 3 * DDIM) / 256, 256>>>(dw1, wh, wl);
    conv_mma_k<DDIM, HDIM, true, 1><<<dim3(STILES, HDIM / 128), 256, CONV_SMEM>>>(
        zqh, zql, wh, wl, db1, d1h, d1l);

    wprep_k<HDIM, HDIM><<<(HDIM * 3 * HDIM) / 256, 256>>>(dw2, wh, wl);
    conv_mma_k<HDIM, HDIM, true, 0><<<dim3(STILES, HDIM / 128), 256, CONV_SMEM>>>(
        d1h, d1l, wh, wl, db2, d2, nullptr);

    dec3_k<<<(BATCH * SLEN) / 8, 256>>>(d2, dw3, db3, x, out);

    fin_k<<<1, 1>>>(out);
}

// round 8
// speedup vs baseline: 1.0315x; 1.0315x over previous
#include <cuda_runtime.h>
#include <cuda_bf16.h>
#include <cstdint>
#include <math_constants.h>

#define BATCH 32
#define SLEN  2048
#define DDIM  128
#define HDIM  256
#define KCODE 512

// ---------------- scratch (static device globals; no allocation) ----------------
__device__ float g_h1[(size_t)BATCH * HDIM * SLEN];   // 64 MB  enc, channel-first
__device__ float g_h2[(size_t)BATCH * HDIM * SLEN];   // 64 MB  enc, channel-first
__device__ float g_z [(size_t)BATCH * DDIM * SLEN];   // 32 MB  channel-first
__device__ float g_zq[(size_t)BATCH * SLEN * DDIM];   // 32 MB  channel-last (feeds MMA dec)
__device__ float g_d1[(size_t)BATCH * SLEN * HDIM];   // 64 MB  dec1 out channel-last
__device__ float g_d2[(size_t)BATCH * SLEN * HDIM];   // 64 MB  dec2 out channel-last
__device__ float g_wh[HDIM * 3 * HDIM];               // K-major weight hi (tf32)
__device__ float g_wl[HDIM * 3 * HDIM];               // K-major weight lo (tf32)
__device__ float g_c2[KCODE];
__device__ double g_acc[2];                            // [0]=sum min dist, [1]=recon SSE

// ---------------- helpers ----------------
__device__ __forceinline__ float tf32_rna(float v) {
    uint32_t o;
    asm("cvt.rna.tf32.f32 %0, %1;" : "=r"(o) : "f"(v));
    return __uint_as_float(o);
}

__device__ __forceinline__ void mma1688_tf32(float* d, const float* a, const float* b) {
    asm volatile(
        "mma.sync.aligned.m16n8k8.row.col.f32.tf32.tf32.f32 "
        "{%0,%1,%2,%3}, {%4,%5,%6,%7}, {%8,%9}, {%0,%1,%2,%3};"
        : "+f"(d[0]), "+f"(d[1]), "+f"(d[2]), "+f"(d[3])
        : "r"(__float_as_uint(a[0])), "r"(__float_as_uint(a[1])),
          "r"(__float_as_uint(a[2])), "r"(__float_as_uint(a[3])),
          "r"(__float_as_uint(b[0])), "r"(__float_as_uint(b[1])));
}

// ---------------- init ----------------
__global__ void init_k() {
    if (threadIdx.x < 2) g_acc[threadIdx.x] = 0.0;
}

// ---------------- codebook norms ----------------
__global__ void c2_k(const float* __restrict__ cb) {
    int k = blockIdx.x * blockDim.x + threadIdx.x;
    if (k < KCODE) {
        const float* r = cb + (size_t)k * DDIM;
        float s = 0.f;
        #pragma unroll 8
        for (int d = 0; d < DDIM; d++) s += r[d] * r[d];
        g_c2[k] = s;
    }
}

// ---------------- encoder conv1: 1 -> H, k=3, SAME, lrelu (round-1 proven) ---
__global__ __launch_bounds__(256) void enc1_k(const float* __restrict__ x,
                                              const float* __restrict__ w,
                                              const float* __restrict__ bias) {
    size_t idx = (size_t)blockIdx.x * blockDim.x + threadIdx.x;   // over B*H*S
    int s = idx & (SLEN - 1);
    int c = (idx >> 11) & (HDIM - 1);
    int b = idx >> 19;
    const float* xb = x + (size_t)b * SLEN;
    float v = bias[c];
    float w0 = w[c*3+0], w1 = w[c*3+1], w2 = w[c*3+2];
    if (s > 0)        v += w0 * xb[s-1];
    v += w1 * xb[s];
    if (s < SLEN - 1) v += w2 * xb[s+1];
    g_h1[idx] = (v >= 0.f) ? v : 0.2f * v;
}

// ------------ SIMT fp32 conv (round-1 proven): channel-first ------------
template<int CI, int CO, bool RELU>
__global__ __launch_bounds__(256) void conv_k(const float* __restrict__ in,
                                              const float* __restrict__ w,
                                              const float* __restrict__ bias,
                                              float* __restrict__ out) {
    const int s_tile  = blockIdx.x * 64;
    const int co_base = blockIdx.y * 128;
    const int b       = blockIdx.z;
    const int tid = threadIdx.x;
    const int tx  = tid & 15;    // s group   (4 outputs)
    const int ty  = tid >> 4;    // co group  (8 outputs)

    __shared__ float ws[48 * 130];       // [ci*3+t][co], stride 130
    __shared__ float ins[16][72];        // [ci][sp], sp in 0..65

    float acc[8][4];
    #pragma unroll
    for (int v = 0; v < 8; v++)
        #pragma unroll
        for (int u = 0; u < 4; u++) acc[v][u] = 0.f;

    const float* in_b = in + (size_t)b * CI * SLEN;

    for (int ci0 = 0; ci0 < CI; ci0 += 16) {
        __syncthreads();
        for (int i = tid; i < 16 * 66; i += 256) {
            int ci = i / 66, sp = i - ci * 66;
            int s = s_tile - 1 + sp;
            float v = 0.f;
            if (s >= 0 && s < SLEN) v = in_b[(size_t)(ci0 + ci) * SLEN + s];
            ins[ci][sp] = v;
        }
        for (int i = tid; i < 128 * 48; i += 256) {
            int co = i / 48, j = i - co * 48;            // j = ci_local*3 + t
            ws[j * 130 + co] = w[(size_t)(co_base + co) * (CI * 3) + (size_t)ci0 * 3 + j];
        }
        __syncthreads();

        #pragma unroll
        for (int ci = 0; ci < 16; ci++) {
            float xv[6];
            #pragma unroll
            for (int u = 0; u < 6; u++) xv[u] = ins[ci][tx * 4 + u];
            #pragma unroll
            for (int t = 0; t < 3; t++) {
                float wv[8];
                #pragma unroll
                for (int v = 0; v < 8; v++) wv[v] = ws[(ci * 3 + t) * 130 + ty * 8 + v];
                #pragma unroll
                for (int v = 0; v < 8; v++)
                    #pragma unroll
                    for (int u = 0; u < 4; u++)
                        acc[v][u] += wv[v] * xv[u + t];
            }
        }
    }

    #pragma unroll
    for (int v = 0; v < 8; v++) {
        int co = co_base + ty * 8 + v;
        float bb = bias[co];
        #pragma unroll
        for (int u = 0; u < 4; u++) {
            int s = s_tile + tx * 4 + u;
            float r = acc[v][u] + bb;
            if (RELU) r = (r >= 0.f) ? r : 0.2f * r;
            out[((size_t)b * CO + co) * SLEN + s] = r;
        }
    }
}

// ------- VQ: round-5 arithmetic VERBATIM; 128 threads so zr[] stays in regs -------
__global__ __launch_bounds__(128) void vq_k(const float* __restrict__ cb,
                                            float* __restrict__ out_idx) {
    int gp = blockIdx.x * 128 + threadIdx.x;     // global position in [0, B*S)
    int b = gp >> 11;
    int s = gp & (SLEN - 1);

    const float* zb = g_z + (size_t)b * DDIM * SLEN + s;
    float zr[DDIM];
    #pragma unroll
    for (int d = 0; d < DDIM; d++) zr[d] = zb[(size_t)d * SLEN];

    float z2 = 0.f;
    #pragma unroll
    for (int d = 0; d < DDIM; d++) z2 += zr[d] * zr[d];

    float best = CUDART_INF_F;
    int bi = 0;
    const float4* cb4 = reinterpret_cast<const float4*>(cb);
    for (int k = 0; k < KCODE; k++) {
        float d0 = 0.f, d1 = 0.f, d2 = 0.f, d3 = 0.f;
        #pragma unroll
        for (int q = 0; q < 32; q++) {
            float4 c = __ldg(&cb4[k * 32 + q]);
            d0 += c.x * zr[4*q+0];
            d1 += c.y * zr[4*q+1];
            d2 += c.z * zr[4*q+2];
            d3 += c.w * zr[4*q+3];
        }
        float dist = z2 + __ldg(&g_c2[k]) - 2.f * ((d0 + d1) + (d2 + d3));
        if (dist < best) { best = dist; bi = k; }
    }

    out_idx[gp] = (float)bi;

    // gather z_q (channel-last, coalesced) and exact ||z - c||^2 (round-1 order)
    const float* cc = cb + (size_t)bi * DDIM;
    float4* zq = reinterpret_cast<float4*>(g_zq + (size_t)gp * DDIM);
    float qs = 0.f;
    #pragma unroll
    for (int d = 0; d < DDIM; d++) {
        float df = zr[d] - cc[d];
        qs += df * df;
    }
    #pragma unroll
    for (int q = 0; q < 32; q++) zq[q] = __ldg(reinterpret_cast<const float4*>(cc) + q);

    __shared__ float red[128];
    red[threadIdx.x] = qs;
    __syncthreads();
    for (int off = 64; off > 0; off >>= 1) {
        if (threadIdx.x < off) red[threadIdx.x] += red[threadIdx.x + off];
        __syncthreads();
    }
    if (threadIdx.x == 0) atomicAdd(&g_acc[0], (double)red[0]);
}

// weight prep: [CO][ci*3+t] fp32 -> K-major [CO][t*CI+ci] tf32 hi/lo
template<int CO, int CI>
__global__ __launch_bounds__(256) void wprep_k(const float* __restrict__ w,
                                               float* __restrict__ wh,
                                               float* __restrict__ wl) {
    int idx = blockIdx.x * 256 + threadIdx.x;        // over CO*3*CI
    int co = idx / (3 * CI);
    int r  = idx - co * (3 * CI);                    // = t*CI + ci
    int t  = r / CI;
    int ci = r - t * CI;
    float v = w[(size_t)co * 3 * CI + (size_t)ci * 3 + t];
    float h = tf32_rna(v);
    wh[idx] = h;
    wl[idx] = tf32_rna(v - h);
}

// ============ 3xTF32 HMMA conv (round-5 exact): CI -> CO, k=3 SAME ============
template<int CI, int CO, bool RELU>
__global__ __launch_bounds__(256, 2) void conv_mma_k(const float* __restrict__ in,
                                                     const float* __restrict__ wh,
                                                     const float* __restrict__ wl,
                                                     const float* __restrict__ bias,
                                                     float* __restrict__ out) {
    constexpr int KTOT = 3 * CI;
    constexpr int NCH  = KTOT / 32;
    constexpr int RSTR = 36;                 // floats per smem row (32 + 4 pad)

    extern __shared__ float sm[];
    float* Ah = sm;
    float* Al = sm + 128 * RSTR;
    float* Bh = sm + 2 * 128 * RSTR;
    float* Bl = sm + 3 * 128 * RSTR;

    const int tid  = threadIdx.x;
    const int lane = tid & 31;
    const int wid  = tid >> 5;
    const int wm   = wid & 1;                // 2 warps over co
    const int wn   = wid >> 1;               // 4 warps over p
    const int g    = lane >> 2;              // group id 0..7
    const int t4   = lane & 3;               // thread-in-group 0..3

    const int bs_base = blockIdx.x * 128;
    const int co_base = blockIdx.y * 128;
    const int s_in_b0 = bs_base & (SLEN - 1);

    float acc[4][4][4];
    #pragma unroll
    for (int i = 0; i < 4; i++)
        #pragma unroll
        for (int j = 0; j < 4; j++)
            #pragma unroll
            for (int e = 0; e < 4; e++) acc[i][j][e] = 0.f;

    for (int kc = 0; kc < NCH; kc++) {
        const int t   = (kc * 32) / CI;       // tap (chunk never crosses taps; CI%32==0)
        const int ci0 = (kc * 32) % CI;
        __syncthreads();

        #pragma unroll
        for (int j = 0; j < 4; j++) {
            int idx = tid + 256 * j;          // 1024 float4
            int row = idx >> 3, q = idx & 7;
            size_t src = (size_t)(co_base + row) * KTOT + kc * 32 + 4 * q;
            float4 vh = *reinterpret_cast<const float4*>(wh + src);
            float4 vl = *reinterpret_cast<const float4*>(wl + src);
            *reinterpret_cast<float4*>(Ah + row * RSTR + 4 * q) = vh;
            *reinterpret_cast<float4*>(Al + row * RSTR + 4 * q) = vl;
        }
        #pragma unroll
        for (int j = 0; j < 4; j++) {
            int idx = tid + 256 * j;          // 1024 float4
            int row = idx >> 3, q = idx & 7;
            int sb = s_in_b0 + row + t - 1;
            float4 v = make_float4(0.f, 0.f, 0.f, 0.f);
            if (sb >= 0 && sb < SLEN)
                v = *reinterpret_cast<const float4*>(
                        in + (size_t)(bs_base + row + t - 1) * CI + ci0 + 4 * q);
            float4 h, l;
            h.x = tf32_rna(v.x); l.x = tf32_rna(v.x - h.x);
            h.y = tf32_rna(v.y); l.y = tf32_rna(v.y - h.y);
            h.z = tf32_rna(v.z); l.z = tf32_rna(v.z - h.z);
            h.w = tf32_rna(v.w); l.w = tf32_rna(v.w - h.w);
            *reinterpret_cast<float4*>(Bh + row * RSTR + 4 * q) = h;
            *reinterpret_cast<float4*>(Bl + row * RSTR + 4 * q) = l;
        }
        __syncthreads();

        #pragma unroll
        for (int ks = 0; ks < 4; ks++) {
            const int k0 = ks * 8 + t4;       // this thread's k column
            float bh[4][2], bl[4][2];
            #pragma unroll
            for (int nf = 0; nf < 4; nf++) {
                int nrow = wn * 32 + nf * 8 + g;
                bh[nf][0] = Bh[nrow * RSTR + k0];
                bh[nf][1] = Bh[nrow * RSTR + k0 + 4];
                bl[nf][0] = Bl[nrow * RSTR + k0];
                bl[nf][1] = Bl[nrow * RSTR + k0 + 4];
            }
            #pragma unroll
            for (int mf = 0; mf < 4; mf++) {
                int mrow = wm * 64 + mf * 16 + g;
                float ah[4], al[4];
                ah[0] = Ah[mrow * RSTR + k0];
                ah[1] = Ah[(mrow + 8) * RSTR + k0];
                ah[2] = Ah[mrow * RSTR + k0 + 4];
                ah[3] = Ah[(mrow + 8) * RSTR + k0 + 4];
                al[0] = Al[mrow * RSTR + k0];
                al[1] = Al[(mrow + 8) * RSTR + k0];
                al[2] = Al[mrow * RSTR + k0 + 4];
                al[3] = Al[(mrow + 8) * RSTR + k0 + 4];
                #pragma unroll
                for (int nf = 0; nf < 4; nf++) {
                    mma1688_tf32(acc[mf][nf], ah, bh[nf]);
                    mma1688_tf32(acc[mf][nf], ah, bl[nf]);
                    mma1688_tf32(acc[mf][nf], al, bh[nf]);
                }
            }
        }
    }

    #pragma unroll
    for (int mf = 0; mf < 4; mf++) {
        int co0 = co_base + wm * 64 + mf * 16 + g;
        float bb0 = bias[co0];
        float bb1 = bias[co0 + 8];
        #pragma unroll
        for (int nf = 0; nf < 4; nf++) {
            int p = bs_base + wn * 32 + nf * 8 + t4 * 2;
            #pragma unroll
            for (int e = 0; e < 2; e++) {
                float v0 = acc[mf][nf][e] + bb0;       // row g,   col t4*2+e
                float v1 = acc[mf][nf][2 + e] + bb1;   // row g+8, col t4*2+e
                if (RELU) {
                    v0 = (v0 >= 0.f) ? v0 : 0.2f * v0;
                    v1 = (v1 >= 0.f) ? v1 : 0.2f * v1;
                }
                out[(size_t)(p + e) * CO + co0]     = v0;
                out[(size_t)(p + e) * CO + co0 + 8] = v1;
            }
        }
    }
}

// ---------------- decoder conv3: H -> 1 (channel-last input) + recon loss ----
__global__ __launch_bounds__(256) void dec3_k(const float* __restrict__ hin,
                                              const float* __restrict__ w,
                                              const float* __restrict__ bias,
                                              const float* __restrict__ x,
                                              float* __restrict__ xrec) {
    __shared__ float ws[HDIM * 3];
    for (int i = threadIdx.x; i < HDIM * 3; i += 256) ws[i] = w[i];
    __syncthreads();

    int wid = threadIdx.x >> 5, lane = threadIdx.x & 31;
    int p = blockIdx.x * 8 + wid;     // global position
    int s = p & (SLEN - 1);

    float acc = 0.f;
    #pragma unroll
    for (int t = 0; t < 3; t++) {
        int sb = s + t - 1;
        if (sb < 0 || sb >= SLEN) continue;
        const float4* r = reinterpret_cast<const float4*>(hin + (size_t)(p + t - 1) * HDIM);
        #pragma unroll
        for (int q = 0; q < 2; q++) {
            float4 v = r[lane * 2 + q];
            int c0 = lane * 8 + q * 4;
            acc += v.x * ws[(c0+0)*3+t] + v.y * ws[(c0+1)*3+t]
                 + v.z * ws[(c0+2)*3+t] + v.w * ws[(c0+3)*3+t];
        }
    }
    #pragma unroll
    for (int off = 16; off > 0; off >>= 1)
        acc += __shfl_xor_sync(0xFFFFFFFFu, acc, off);

    __shared__ float wsum[8];
    if (lane == 0) {
        float a = acc + bias[0];
        xrec[p] = a;
        float diff = x[p] - a;
        wsum[wid] = diff * diff;
    }
    __syncthreads();
    if (threadIdx.x == 0) {
        float s8 = 0.f;
        #pragma unroll
        for (int i = 0; i < 8; i++) s8 += wsum[i];
        atomicAdd(&g_acc[1], (double)s8);
    }
}

// ---------------- finalize losses ----------------
__global__ void fin_k(float* __restrict__ out) {
    double qsum = g_acc[0];
    double rsum = g_acc[1];
    float qm    = (float)(qsum / ((double)BATCH * SLEN * DDIM));
    float recon = (float)(rsum / ((double)BATCH * SLEN));
    float vq    = qm * 0.05f;
    float com   = qm * 0.15f;
    size_t base = (size_t)2 * BATCH * SLEN;
    out[base + 0] = recon + vq + com;
    out[base + 1] = recon;
    out[base + 2] = vq;
    out[base + 3] = com;
}

// ---------------- launch ----------------
static const int CONV_SMEM = 4 * 128 * 36 * 4;   // 73728 bytes

extern "C" void kernel_launch(void* const* d_in, const int* in_sizes, int n_in,
                              void* d_out, int out_size) {
    const float* x   = (const float*)d_in[0];
    const float* cb  = (const float*)d_in[1];
    const float* ew1 = (const float*)d_in[2];
    const float* eb1 = (const float*)d_in[3];
    const float* ew2 = (const float*)d_in[4];
    const float* eb2 = (const float*)d_in[5];
    const float* ew3 = (const float*)d_in[6];
    const float* eb3 = (const float*)d_in[7];
    const float* dw1 = (const float*)d_in[8];
    const float* db1 = (const float*)d_in[9];
    const float* dw2 = (const float*)d_in[10];
    const float* db2 = (const float*)d_in[11];
    const float* dw3 = (const float*)d_in[12];
    const float* db3 = (const float*)d_in[13];
    float* out = (float*)d_out;

    float *h1, *h2, *z, *zq, *d1, *d2, *wh, *wl;
    cudaGetSymbolAddress((void**)&h1, g_h1);
    cudaGetSymbolAddress((void**)&h2, g_h2);
    cudaGetSymbolAddress((void**)&z,  g_z);
    cudaGetSymbolAddress((void**)&zq, g_zq);
    cudaGetSymbolAddress((void**)&d1, g_d1);
    cudaGetSymbolAddress((void**)&d2, g_d2);
    cudaGetSymbolAddress((void**)&wh, g_wh);
    cudaGetSymbolAddress((void**)&wl, g_wl);

    cudaFuncSetAttribute(conv_mma_k<DDIM, HDIM, true>,
                         cudaFuncAttributeMaxDynamicSharedMemorySize, CONV_SMEM);
    cudaFuncSetAttribute(conv_mma_k<HDIM, HDIM, true>,
                         cudaFuncAttributeMaxDynamicSharedMemorySize, CONV_SMEM);

    init_k<<<1, 32>>>();
    c2_k<<<2, 256>>>(cb);

    // ---------- encoder: round-5 proven fp32 path (channel-first) ----------
    enc1_k<<<(BATCH * HDIM * SLEN) / 256, 256>>>(x, ew1, eb1);

    dim3 g2(SLEN / 64, HDIM / 128, BATCH);
    conv_k<HDIM, HDIM, true><<<g2, 256>>>(h1, ew2, eb2, h2);

    dim3 g3(SLEN / 64, DDIM / 128, BATCH);
    conv_k<HDIM, DDIM, false><<<g3, 256>>>(h2, ew3, eb3, z);

    // ---------- VQ: identical arithmetic, 128-thread blocks (no reg spill) ----------
    vq_k<<<(BATCH * SLEN) / 128, 128>>>(cb, out + (size_t)BATCH * SLEN);

    // ---------- decoder: 3xTF32 MMA (round-5 exact) ----------
    const int STILES = (BATCH * SLEN) / 128;   // 512

    wprep_k<HDIM, DDIM><<<(HDIM * 3 * DDIM) / 256, 256>>>(dw1, wh, wl);
    conv_mma_k<DDIM, HDIM, true><<<dim3(STILES, HDIM / 128), 256, CONV_SMEM>>>(
        zq, wh, wl, db1, d1);

    wprep_k<HDIM, HDIM><<<(HDIM * 3 * HDIM) / 256, 256>>>(dw2, wh, wl);
    conv_mma_k<HDIM, HDIM, true><<<dim3(STILES, HDIM / 128), 256, CONV_SMEM>>>(
        d1, wh, wl, db2, d2);

    dec3_k<<<(BATCH * SLEN) / 8, 256>>>(d2, dw3, db3, x, out);

    fin_k<<<1, 1>>>(out);
}

// round 10
// speedup vs baseline: 1.6634x; 1.6126x over previous
#include <cuda_runtime.h>
#include <cuda_bf16.h>
#include <cstdint>
#include <math_constants.h>

#define BATCH 32
#define SLEN  2048
#define DDIM  128
#define HDIM  256
#define KCODE 512

// ---------------- scratch (static device globals; no allocation) ----------------
__device__ float g_h1[(size_t)BATCH * HDIM * SLEN];   // 64 MB  enc, channel-first
__device__ float g_h2[(size_t)BATCH * HDIM * SLEN];   // 64 MB  enc, channel-first
__device__ float g_z [(size_t)BATCH * DDIM * SLEN];   // 32 MB  channel-first
__device__ float g_zq[(size_t)BATCH * SLEN * DDIM];   // 32 MB  channel-last (feeds MMA dec)
__device__ float g_d1[(size_t)BATCH * SLEN * HDIM];   // 64 MB  dec1 out channel-last
__device__ float g_d2[(size_t)BATCH * SLEN * HDIM];   // 64 MB  dec2 out channel-last
__device__ float g_wh[HDIM * 3 * HDIM];               // K-major weight hi (tf32)
__device__ float g_wl[HDIM * 3 * HDIM];               // K-major weight lo (tf32)
__device__ float g_c2[KCODE];
__device__ double g_acc[2];                            // [0]=sum min dist, [1]=recon SSE

// ---------------- helpers ----------------
__device__ __forceinline__ float tf32_rna(float v) {
    uint32_t o;
    asm("cvt.rna.tf32.f32 %0, %1;" : "=r"(o) : "f"(v));
    return __uint_as_float(o);
}

__device__ __forceinline__ void mma1688_tf32(float* d, const float* a, const float* b) {
    asm volatile(
        "mma.sync.aligned.m16n8k8.row.col.f32.tf32.tf32.f32 "
        "{%0,%1,%2,%3}, {%4,%5,%6,%7}, {%8,%9}, {%0,%1,%2,%3};"
        : "+f"(d[0]), "+f"(d[1]), "+f"(d[2]), "+f"(d[3])
        : "r"(__float_as_uint(a[0])), "r"(__float_as_uint(a[1])),
          "r"(__float_as_uint(a[2])), "r"(__float_as_uint(a[3])),
          "r"(__float_as_uint(b[0])), "r"(__float_as_uint(b[1])));
}

// ---------------- init ----------------
__global__ void init_k() {
    if (threadIdx.x < 2) g_acc[threadIdx.x] = 0.0;
}

// ---------------- codebook norms ----------------
__global__ void c2_k(const float* __restrict__ cb) {
    int k = blockIdx.x * blockDim.x + threadIdx.x;
    if (k < KCODE) {
        const float* r = cb + (size_t)k * DDIM;
        float s = 0.f;
        #pragma unroll 8
        for (int d = 0; d < DDIM; d++) s += r[d] * r[d];
        g_c2[k] = s;
    }
}

// ---------------- encoder conv1: 1 -> H, k=3, SAME, lrelu (round-1 proven) ---
__global__ __launch_bounds__(256) void enc1_k(const float* __restrict__ x,
                                              const float* __restrict__ w,
                                              const float* __restrict__ bias) {
    size_t idx = (size_t)blockIdx.x * blockDim.x + threadIdx.x;   // over B*H*S
    int s = idx & (SLEN - 1);
    int c = (idx >> 11) & (HDIM - 1);
    int b = idx >> 19;
    const float* xb = x + (size_t)b * SLEN;
    float v = bias[c];
    float w0 = w[c*3+0], w1 = w[c*3+1], w2 = w[c*3+2];
    if (s > 0)        v += w0 * xb[s-1];
    v += w1 * xb[s];
    if (s < SLEN - 1) v += w2 * xb[s+1];
    g_h1[idx] = (v >= 0.f) ? v : 0.2f * v;
}

// ------------ SIMT fp32 conv (round-1 proven): channel-first ------------
template<int CI, int CO, bool RELU>
__global__ __launch_bounds__(256) void conv_k(const float* __restrict__ in,
                                              const float* __restrict__ w,
                                              const float* __restrict__ bias,
                                              float* __restrict__ out) {
    const int s_tile  = blockIdx.x * 64;
    const int co_base = blockIdx.y * 128;
    const int b       = blockIdx.z;
    const int tid = threadIdx.x;
    const int tx  = tid & 15;    // s group   (4 outputs)
    const int ty  = tid >> 4;    // co group  (8 outputs)

    __shared__ float ws[48 * 130];       // [ci*3+t][co], stride 130
    __shared__ float ins[16][72];        // [ci][sp], sp in 0..65

    float acc[8][4];
    #pragma unroll
    for (int v = 0; v < 8; v++)
        #pragma unroll
        for (int u = 0; u < 4; u++) acc[v][u] = 0.f;

    const float* in_b = in + (size_t)b * CI * SLEN;

    for (int ci0 = 0; ci0 < CI; ci0 += 16) {
        __syncthreads();
        for (int i = tid; i < 16 * 66; i += 256) {
            int ci = i / 66, sp = i - ci * 66;
            int s = s_tile - 1 + sp;
            float v = 0.f;
            if (s >= 0 && s < SLEN) v = in_b[(size_t)(ci0 + ci) * SLEN + s];
            ins[ci][sp] = v;
        }
        for (int i = tid; i < 128 * 48; i += 256) {
            int co = i / 48, j = i - co * 48;            // j = ci_local*3 + t
            ws[j * 130 + co] = w[(size_t)(co_base + co) * (CI * 3) + (size_t)ci0 * 3 + j];
        }
        __syncthreads();

        #pragma unroll
        for (int ci = 0; ci < 16; ci++) {
            float xv[6];
            #pragma unroll
            for (int u = 0; u < 6; u++) xv[u] = ins[ci][tx * 4 + u];
            #pragma unroll
            for (int t = 0; t < 3; t++) {
                float wv[8];
                #pragma unroll
                for (int v = 0; v < 8; v++) wv[v] = ws[(ci * 3 + t) * 130 + ty * 8 + v];
                #pragma unroll
                for (int v = 0; v < 8; v++)
                    #pragma unroll
                    for (int u = 0; u < 4; u++)
                        acc[v][u] += wv[v] * xv[u + t];
            }
        }
    }

    #pragma unroll
    for (int v = 0; v < 8; v++) {
        int co = co_base + ty * 8 + v;
        float bb = bias[co];
        #pragma unroll
        for (int u = 0; u < 4; u++) {
            int s = s_tile + tx * 4 + u;
            float r = acc[v][u] + bb;
            if (RELU) r = (r >= 0.f) ? r : 0.2f * r;
            out[((size_t)b * CO + co) * SLEN + s] = r;
        }
    }
}

// ------- VQ: round-5 arithmetic BIT-EXACT; codebook staged via smem chunks -------
__global__ __launch_bounds__(256) void vq_k(const float* __restrict__ cb,
                                            float* __restrict__ out_idx) {
    __shared__ float4 cbs[64 * 32];      // 64 codes x 128 floats = 32 KB
    __shared__ float  c2s[64];

    int gp = blockIdx.x * 256 + threadIdx.x;     // global position in [0, B*S)
    int b = gp >> 11;
    int s = gp & (SLEN - 1);

    const float* zb = g_z + (size_t)b * DDIM * SLEN + s;
    float zr[DDIM];
    #pragma unroll
    for (int d = 0; d < DDIM; d++) zr[d] = zb[(size_t)d * SLEN];

    float z2 = 0.f;
    #pragma unroll
    for (int d = 0; d < DDIM; d++) z2 += zr[d] * zr[d];

    float best = CUDART_INF_F;
    int bi = 0;
    const float4* cb4 = reinterpret_cast<const float4*>(cb);

    for (int kc = 0; kc < KCODE; kc += 64) {
        __syncthreads();
        // cooperative coalesced stage of 64 codes (+ their norms)
        #pragma unroll
        for (int i = threadIdx.x; i < 64 * 32; i += 256)
            cbs[i] = cb4[kc * 32 + i];
        if (threadIdx.x < 64) c2s[threadIdx.x] = g_c2[kc + threadIdx.x];
        __syncthreads();

        for (int kk = 0; kk < 64; kk++) {
            float d0 = 0.f, d1 = 0.f, d2 = 0.f, d3 = 0.f;
            #pragma unroll
            for (int q = 0; q < 32; q++) {
                float4 c = cbs[kk * 32 + q];
                d0 += c.x * zr[4*q+0];
                d1 += c.y * zr[4*q+1];
                d2 += c.z * zr[4*q+2];
                d3 += c.w * zr[4*q+3];
            }
            float dist = z2 + c2s[kk] - 2.f * ((d0 + d1) + (d2 + d3));
            if (dist < best) { best = dist; bi = kc + kk; }
        }
    }

    out_idx[gp] = (float)bi;

    // gather z_q (channel-last, coalesced) and exact ||z - c||^2 (round-1 order)
    const float* cc = cb + (size_t)bi * DDIM;
    float4* zq = reinterpret_cast<float4*>(g_zq + (size_t)gp * DDIM);
    float qs = 0.f;
    #pragma unroll
    for (int d = 0; d < DDIM; d++) {
        float df = zr[d] - cc[d];
        qs += df * df;
    }
    #pragma unroll
    for (int q = 0; q < 32; q++) zq[q] = __ldg(reinterpret_cast<const float4*>(cc) + q);

    __shared__ float red[256];
    red[threadIdx.x] = qs;
    __syncthreads();
    for (int off = 128; off > 0; off >>= 1) {
        if (threadIdx.x < off) red[threadIdx.x] += red[threadIdx.x + off];
        __syncthreads();
    }
    if (threadIdx.x == 0) atomicAdd(&g_acc[0], (double)red[0]);
}

// weight prep: [CO][ci*3+t] fp32 -> K-major [CO][t*CI+ci] tf32 hi/lo
template<int CO, int CI>
__global__ __launch_bounds__(256) void wprep_k(const float* __restrict__ w,
                                               float* __restrict__ wh,
                                               float* __restrict__ wl) {
    int idx = blockIdx.x * 256 + threadIdx.x;        // over CO*3*CI
    int co = idx / (3 * CI);
    int r  = idx - co * (3 * CI);                    // = t*CI + ci
    int t  = r / CI;
    int ci = r - t * CI;
    float v = w[(size_t)co * 3 * CI + (size_t)ci * 3 + t];
    float h = tf32_rna(v);
    wh[idx] = h;
    wl[idx] = tf32_rna(v - h);
}

// ============ 3xTF32 HMMA conv (round-5 exact): CI -> CO, k=3 SAME ============
template<int CI, int CO, bool RELU>
__global__ __launch_bounds__(256, 2) void conv_mma_k(const float* __restrict__ in,
                                                     const float* __restrict__ wh,
                                                     const float* __restrict__ wl,
                                                     const float* __restrict__ bias,
                                                     float* __restrict__ out) {
    constexpr int KTOT = 3 * CI;
    constexpr int NCH  = KTOT / 32;
    constexpr int RSTR = 36;                 // floats per smem row (32 + 4 pad)

    extern __shared__ float sm[];
    float* Ah = sm;
    float* Al = sm + 128 * RSTR;
    float* Bh = sm + 2 * 128 * RSTR;
    float* Bl = sm + 3 * 128 * RSTR;

    const int tid  = threadIdx.x;
    const int lane = tid & 31;
    const int wid  = tid >> 5;
    const int wm   = wid & 1;                // 2 warps over co
    const int wn   = wid >> 1;               // 4 warps over p
    const int g    = lane >> 2;              // group id 0..7
    const int t4   = lane & 3;               // thread-in-group 0..3

    const int bs_base = blockIdx.x * 128;
    const int co_base = blockIdx.y * 128;
    const int s_in_b0 = bs_base & (SLEN - 1);

    float acc[4][4][4];
    #pragma unroll
    for (int i = 0; i < 4; i++)
        #pragma unroll
        for (int j = 0; j < 4; j++)
            #pragma unroll
            for (int e = 0; e < 4; e++) acc[i][j][e] = 0.f;

    for (int kc = 0; kc < NCH; kc++) {
        const int t   = (kc * 32) / CI;       // tap (chunk never crosses taps; CI%32==0)
        const int ci0 = (kc * 32) % CI;
        __syncthreads();

        #pragma unroll
        for (int j = 0; j < 4; j++) {
            int idx = tid + 256 * j;          // 1024 float4
            int row = idx >> 3, q = idx & 7;
            size_t src = (size_t)(co_base + row) * KTOT + kc * 32 + 4 * q;
            float4 vh = *reinterpret_cast<const float4*>(wh + src);
            float4 vl = *reinterpret_cast<const float4*>(wl + src);
            *reinterpret_cast<float4*>(Ah + row * RSTR + 4 * q) = vh;
            *reinterpret_cast<float4*>(Al + row * RSTR + 4 * q) = vl;
        }
        #pragma unroll
        for (int j = 0; j < 4; j++) {
            int idx = tid + 256 * j;          // 1024 float4
            int row = idx >> 3, q = idx & 7;
            int sb = s_in_b0 + row + t - 1;
            float4 v = make_float4(0.f, 0.f, 0.f, 0.f);
            if (sb >= 0 && sb < SLEN)
                v = *reinterpret_cast<const float4*>(
                        in + (size_t)(bs_base + row + t - 1) * CI + ci0 + 4 * q);
            float4 h, l;
            h.x = tf32_rna(v.x); l.x = tf32_rna(v.x - h.x);
            h.y = tf32_rna(v.y); l.y = tf32_rna(v.y - h.y);
            h.z = tf32_rna(v.z); l.z = tf32_rna(v.z - h.z);
            h.w = tf32_rna(v.w); l.w = tf32_rna(v.w - h.w);
            *reinterpret_cast<float4*>(Bh + row * RSTR + 4 * q) = h;
            *reinterpret_cast<float4*>(Bl + row * RSTR + 4 * q) = l;
        }
        __syncthreads();

        #pragma unroll
        for (int ks = 0; ks < 4; ks++) {
            const int k0 = ks * 8 + t4;       // this thread's k column
            float bh[4][2], bl[4][2];
            #pragma unroll
            for (int nf = 0; nf < 4; nf++) {
                int nrow = wn * 32 + nf * 8 + g;
                bh[nf][0] = Bh[nrow * RSTR + k0];
                bh[nf][1] = Bh[nrow * RSTR + k0 + 4];
                bl[nf][0] = Bl[nrow * RSTR + k0];
                bl[nf][1] = Bl[nrow * RSTR + k0 + 4];
            }
            #pragma unroll
            for (int mf = 0; mf < 4; mf++) {
                int mrow = wm * 64 + mf * 16 + g;
                float ah[4], al[4];
                ah[0] = Ah[mrow * RSTR + k0];
                ah[1] = Ah[(mrow + 8) * RSTR + k0];
                ah[2] = Ah[mrow * RSTR + k0 + 4];
                ah[3] = Ah[(mrow + 8) * RSTR + k0 + 4];
                al[0] = Al[mrow * RSTR + k0];
                al[1] = Al[(mrow + 8) * RSTR + k0];
                al[2] = Al[mrow * RSTR + k0 + 4];
                al[3] = Al[(mrow + 8) * RSTR + k0 + 4];
                #pragma unroll
                for (int nf = 0; nf < 4; nf++) {
                    mma1688_tf32(acc[mf][nf], ah, bh[nf]);
                    mma1688_tf32(acc[mf][nf], ah, bl[nf]);
                    mma1688_tf32(acc[mf][nf], al, bh[nf]);
                }
            }
        }
    }

    #pragma unroll
    for (int mf = 0; mf < 4; mf++) {
        int co0 = co_base + wm * 64 + mf * 16 + g;
        float bb0 = bias[co0];
        float bb1 = bias[co0 + 8];
        #pragma unroll
        for (int nf = 0; nf < 4; nf++) {
            int p = bs_base + wn * 32 + nf * 8 + t4 * 2;
            #pragma unroll
            for (int e = 0; e < 2; e++) {
                float v0 = acc[mf][nf][e] + bb0;       // row g,   col t4*2+e
                float v1 = acc[mf][nf][2 + e] + bb1;   // row g+8, col t4*2+e
                if (RELU) {
                    v0 = (v0 >= 0.f) ? v0 : 0.2f * v0;
                    v1 = (v1 >= 0.f) ? v1 : 0.2f * v1;
                }
                out[(size_t)(p + e) * CO + co0]     = v0;
                out[(size_t)(p + e) * CO + co0 + 8] = v1;
            }
        }
    }
}

// ---------------- decoder conv3: H -> 1 (channel-last input) + recon loss ----
__global__ __launch_bounds__(256) void dec3_k(const float* __restrict__ hin,
                                              const float* __restrict__ w,
                                              const float* __restrict__ bias,
                                              const float* __restrict__ x,
                                              float* __restrict__ xrec) {
    __shared__ float ws[HDIM * 3];
    for (int i = threadIdx.x; i < HDIM * 3; i += 256) ws[i] = w[i];
    __syncthreads();

    int wid = threadIdx.x >> 5, lane = threadIdx.x & 31;
    int p = blockIdx.x * 8 + wid;     // global position
    int s = p & (SLEN - 1);

    float acc = 0.f;
    #pragma unroll
    for (int t = 0; t < 3; t++) {
        int sb = s + t - 1;
        if (sb < 0 || sb >= SLEN) continue;
        const float4* r = reinterpret_cast<const float4*>(hin + (size_t)(p + t - 1) * HDIM);
        #pragma unroll
        for (int q = 0; q < 2; q++) {
            float4 v = r[lane * 2 + q];
            int c0 = lane * 8 + q * 4;
            acc += v.x * ws[(c0+0)*3+t] + v.y * ws[(c0+1)*3+t]
                 + v.z * ws[(c0+2)*3+t] + v.w * ws[(c0+3)*3+t];
        }
    }
    #pragma unroll
    for (int off = 16; off > 0; off >>= 1)
        acc += __shfl_xor_sync(0xFFFFFFFFu, acc, off);

    __shared__ float wsum[8];
    if (lane == 0) {
        float a = acc + bias[0];
        xrec[p] = a;
        float diff = x[p] - a;
        wsum[wid] = diff * diff;
    }
    __syncthreads();
    if (threadIdx.x == 0) {
        float s8 = 0.f;
        #pragma unroll
        for (int i = 0; i < 8; i++) s8 += wsum[i];
        atomicAdd(&g_acc[1], (double)s8);
    }
}

// ---------------- finalize losses ----------------
__global__ void fin_k(float* __restrict__ out) {
    double qsum = g_acc[0];
    double rsum = g_acc[1];
    float qm    = (float)(qsum / ((double)BATCH * SLEN * DDIM));
    float recon = (float)(rsum / ((double)BATCH * SLEN));
    float vq    = qm * 0.05f;
    float com   = qm * 0.15f;
    size_t base = (size_t)2 * BATCH * SLEN;
    out[base + 0] = recon + vq + com;
    out[base + 1] = recon;
    out[base + 2] = vq;
    out[base + 3] = com;
}

// ---------------- launch ----------------
static const int CONV_SMEM = 4 * 128 * 36 * 4;   // 73728 bytes

extern "C" void kernel_launch(void* const* d_in, const int* in_sizes, int n_in,
                              void* d_out, int out_size) {
    const float* x   = (const float*)d_in[0];
    const float* cb  = (const float*)d_in[1];
    const float* ew1 = (const float*)d_in[2];
    const float* eb1 = (const float*)d_in[3];
    const float* ew2 = (const float*)d_in[4];
    const float* eb2 = (const float*)d_in[5];
    const float* ew3 = (const float*)d_in[6];
    const float* eb3 = (const float*)d_in[7];
    const float* dw1 = (const float*)d_in[8];
    const float* db1 = (const float*)d_in[9];
    const float* dw2 = (const float*)d_in[10];
    const float* db2 = (const float*)d_in[11];
    const float* dw3 = (const float*)d_in[12];
    const float* db3 = (const float*)d_in[13];
    float* out = (float*)d_out;

    float *h1, *h2, *z, *zq, *d1, *d2, *wh, *wl;
    cudaGetSymbolAddress((void**)&h1, g_h1);
    cudaGetSymbolAddress((void**)&h2, g_h2);
    cudaGetSymbolAddress((void**)&z,  g_z);
    cudaGetSymbolAddress((void**)&zq, g_zq);
    cudaGetSymbolAddress((void**)&d1, g_d1);
    cudaGetSymbolAddress((void**)&d2, g_d2);
    cudaGetSymbolAddress((void**)&wh, g_wh);
    cudaGetSymbolAddress((void**)&wl, g_wl);

    cudaFuncSetAttribute(conv_mma_k<DDIM, HDIM, true>,
                         cudaFuncAttributeMaxDynamicSharedMemorySize, CONV_SMEM);
    cudaFuncSetAttribute(conv_mma_k<HDIM, HDIM, true>,
                         cudaFuncAttributeMaxDynamicSharedMemorySize, CONV_SMEM);

    init_k<<<1, 32>>>();
    c2_k<<<2, 256>>>(cb);

    // ---------- encoder: round-5 proven fp32 path (channel-first) ----------
    enc1_k<<<(BATCH * HDIM * SLEN) / 256, 256>>>(x, ew1, eb1);

    dim3 g2(SLEN / 64, HDIM / 128, BATCH);
    conv_k<HDIM, HDIM, true><<<g2, 256>>>(h1, ew2, eb2, h2);

    dim3 g3(SLEN / 64, DDIM / 128, BATCH);
    conv_k<HDIM, DDIM, false><<<g3, 256>>>(h2, ew3, eb3, z);

    // ---------- VQ: bit-exact round-5 arithmetic, smem-staged codebook ----------
    vq_k<<<(BATCH * SLEN) / 256, 256>>>(cb, out + (size_t)BATCH * SLEN);

    // ---------- decoder: 3xTF32 MMA (round-5 exact) ----------
    const int STILES = (BATCH * SLEN) / 128;   // 512

    wprep_k<HDIM, DDIM><<<(HDIM * 3 * DDIM) / 256, 256>>>(dw1, wh, wl);
    conv_mma_k<DDIM, HDIM, true><<<dim3(STILES, HDIM / 128), 256, CONV_SMEM>>>(
        zq, wh, wl, db1, d1);

    wprep_k<HDIM, HDIM><<<(HDIM * 3 * HDIM) / 256, 256>>>(dw2, wh, wl);
    conv_mma_k<HDIM, HDIM, true><<<dim3(STILES, HDIM / 128), 256, CONV_SMEM>>>(
        d1, wh, wl, db2, d2);

    dec3_k<<<(BATCH * SLEN) / 8, 256>>>(d2, dw3, db3, x, out);

    fin_k<<<1, 1>>>(out);
}

// round 11
// speedup vs baseline: 1.8444x; 1.1088x over previous
#include <cuda_runtime.h>
#include <cuda_bf16.h>
#include <cstdint>
#include <math_constants.h>

#define BATCH 32
#define SLEN  2048
#define DDIM  128
#define HDIM  256
#define KCODE 512

// ---------------- scratch (static device globals; no allocation) ----------------
__device__ float g_h1[(size_t)BATCH * HDIM * SLEN];   // 64 MB  enc, channel-first
__device__ float g_h2[(size_t)BATCH * HDIM * SLEN];   // 64 MB  enc, channel-first
__device__ float g_z [(size_t)BATCH * DDIM * SLEN];   // 32 MB  channel-first
__device__ float g_zq[(size_t)BATCH * SLEN * DDIM];   // 32 MB  channel-last (feeds MMA dec)
__device__ float g_d1[(size_t)BATCH * SLEN * HDIM];   // 64 MB  dec1 out channel-last
__device__ float g_d2[(size_t)BATCH * SLEN * HDIM];   // 64 MB  dec2 out channel-last
__device__ __nv_bfloat16 g_wh[HDIM * 3 * HDIM];       // K-major weight hi (bf16)
__device__ __nv_bfloat16 g_wl[HDIM * 3 * HDIM];       // K-major weight lo (bf16)
__device__ float g_c2[KCODE];
__device__ double g_acc[2];                            // [0]=sum min dist, [1]=recon SSE

// ---------------- helpers ----------------
__device__ __forceinline__ uint32_t pack_hi(float v0, float v1, float& r0, float& r1) {
    __nv_bfloat16 h0 = __float2bfloat16_rn(v0);
    __nv_bfloat16 h1 = __float2bfloat16_rn(v1);
    r0 = v0 - __bfloat162float(h0);
    r1 = v1 - __bfloat162float(h1);
    return ((uint32_t)__bfloat16_as_ushort(h1) << 16) | (uint32_t)__bfloat16_as_ushort(h0);
}
__device__ __forceinline__ uint32_t pack_lo(float r0, float r1) {
    __nv_bfloat16 l0 = __float2bfloat16_rn(r0);
    __nv_bfloat16 l1 = __float2bfloat16_rn(r1);
    return ((uint32_t)__bfloat16_as_ushort(l1) << 16) | (uint32_t)__bfloat16_as_ushort(l0);
}

__device__ __forceinline__ void mma16816(float* d, const uint32_t* a, const uint32_t* b) {
    asm volatile(
        "mma.sync.aligned.m16n8k16.row.col.f32.bf16.bf16.f32 "
        "{%0,%1,%2,%3}, {%4,%5,%6,%7}, {%8,%9}, {%0,%1,%2,%3};"
        : "+f"(d[0]), "+f"(d[1]), "+f"(d[2]), "+f"(d[3])
        : "r"(a[0]), "r"(a[1]), "r"(a[2]), "r"(a[3]), "r"(b[0]), "r"(b[1]));
}

// ---------------- init ----------------
__global__ void init_k() {
    if (threadIdx.x < 2) g_acc[threadIdx.x] = 0.0;
}

// ---------------- codebook norms ----------------
__global__ void c2_k(const float* __restrict__ cb) {
    int k = blockIdx.x * blockDim.x + threadIdx.x;
    if (k < KCODE) {
        const float* r = cb + (size_t)k * DDIM;
        float s = 0.f;
        #pragma unroll 8
        for (int d = 0; d < DDIM; d++) s += r[d] * r[d];
        g_c2[k] = s;
    }
}

// ---------------- encoder conv1: 1 -> H, k=3, SAME, lrelu (round-1 proven) ---
__global__ __launch_bounds__(256) void enc1_k(const float* __restrict__ x,
                                              const float* __restrict__ w,
                                              const float* __restrict__ bias) {
    size_t idx = (size_t)blockIdx.x * blockDim.x + threadIdx.x;   // over B*H*S
    int s = idx & (SLEN - 1);
    int c = (idx >> 11) & (HDIM - 1);
    int b = idx >> 19;
    const float* xb = x + (size_t)b * SLEN;
    float v = bias[c];
    float w0 = w[c*3+0], w1 = w[c*3+1], w2 = w[c*3+2];
    if (s > 0)        v += w0 * xb[s-1];
    v += w1 * xb[s];
    if (s < SLEN - 1) v += w2 * xb[s+1];
    g_h1[idx] = (v >= 0.f) ? v : 0.2f * v;
}

// ------------ SIMT fp32 conv (round-1 proven): channel-first ------------
template<int CI, int CO, bool RELU>
__global__ __launch_bounds__(256) void conv_k(const float* __restrict__ in,
                                              const float* __restrict__ w,
                                              const float* __restrict__ bias,
                                              float* __restrict__ out) {
    const int s_tile  = blockIdx.x * 64;
    const int co_base = blockIdx.y * 128;
    const int b       = blockIdx.z;
    const int tid = threadIdx.x;
    const int tx  = tid & 15;    // s group   (4 outputs)
    const int ty  = tid >> 4;    // co group  (8 outputs)

    __shared__ float ws[48 * 130];       // [ci*3+t][co], stride 130
    __shared__ float ins[16][72];        // [ci][sp], sp in 0..65

    float acc[8][4];
    #pragma unroll
    for (int v = 0; v < 8; v++)
        #pragma unroll
        for (int u = 0; u < 4; u++) acc[v][u] = 0.f;

    const float* in_b = in + (size_t)b * CI * SLEN;

    for (int ci0 = 0; ci0 < CI; ci0 += 16) {
        __syncthreads();
        for (int i = tid; i < 16 * 66; i += 256) {
            int ci = i / 66, sp = i - ci * 66;
            int s = s_tile - 1 + sp;
            float v = 0.f;
            if (s >= 0 && s < SLEN) v = in_b[(size_t)(ci0 + ci) * SLEN + s];
            ins[ci][sp] = v;
        }
        for (int i = tid; i < 128 * 48; i += 256) {
            int co = i / 48, j = i - co * 48;            // j = ci_local*3 + t
            ws[j * 130 + co] = w[(size_t)(co_base + co) * (CI * 3) + (size_t)ci0 * 3 + j];
        }
        __syncthreads();

        #pragma unroll
        for (int ci = 0; ci < 16; ci++) {
            float xv[6];
            #pragma unroll
            for (int u = 0; u < 6; u++) xv[u] = ins[ci][tx * 4 + u];
            #pragma unroll
            for (int t = 0; t < 3; t++) {
                float wv[8];
                #pragma unroll
                for (int v = 0; v < 8; v++) wv[v] = ws[(ci * 3 + t) * 130 + ty * 8 + v];
                #pragma unroll
                for (int v = 0; v < 8; v++)
                    #pragma unroll
                    for (int u = 0; u < 4; u++)
                        acc[v][u] += wv[v] * xv[u + t];
            }
        }
    }

    #pragma unroll
    for (int v = 0; v < 8; v++) {
        int co = co_base + ty * 8 + v;
        float bb = bias[co];
        #pragma unroll
        for (int u = 0; u < 4; u++) {
            int s = s_tile + tx * 4 + u;
            float r = acc[v][u] + bb;
            if (RELU) r = (r >= 0.f) ? r : 0.2f * r;
            out[((size_t)b * CO + co) * SLEN + s] = r;
        }
    }
}

// ------- VQ: round-10 proven (bit-exact argmin, smem-staged codebook) -------
__global__ __launch_bounds__(256) void vq_k(const float* __restrict__ cb,
                                            float* __restrict__ out_idx) {
    __shared__ float4 cbs[64 * 32];      // 64 codes x 128 floats = 32 KB
    __shared__ float  c2s[64];

    int gp = blockIdx.x * 256 + threadIdx.x;     // global position in [0, B*S)
    int b = gp >> 11;
    int s = gp & (SLEN - 1);

    const float* zb = g_z + (size_t)b * DDIM * SLEN + s;
    float zr[DDIM];
    #pragma unroll
    for (int d = 0; d < DDIM; d++) zr[d] = zb[(size_t)d * SLEN];

    float z2 = 0.f;
    #pragma unroll
    for (int d = 0; d < DDIM; d++) z2 += zr[d] * zr[d];

    float best = CUDART_INF_F;
    int bi = 0;
    const float4* cb4 = reinterpret_cast<const float4*>(cb);

    for (int kc = 0; kc < KCODE; kc += 64) {
        __syncthreads();
        #pragma unroll
        for (int i = threadIdx.x; i < 64 * 32; i += 256)
            cbs[i] = cb4[kc * 32 + i];
        if (threadIdx.x < 64) c2s[threadIdx.x] = g_c2[kc + threadIdx.x];
        __syncthreads();

        for (int kk = 0; kk < 64; kk++) {
            float d0 = 0.f, d1 = 0.f, d2 = 0.f, d3 = 0.f;
            #pragma unroll
            for (int q = 0; q < 32; q++) {
                float4 c = cbs[kk * 32 + q];
                d0 += c.x * zr[4*q+0];
                d1 += c.y * zr[4*q+1];
                d2 += c.z * zr[4*q+2];
                d3 += c.w * zr[4*q+3];
            }
            float dist = z2 + c2s[kk] - 2.f * ((d0 + d1) + (d2 + d3));
            if (dist < best) { best = dist; bi = kc + kk; }
        }
    }

    out_idx[gp] = (float)bi;

    const float* cc = cb + (size_t)bi * DDIM;
    float4* zq = reinterpret_cast<float4*>(g_zq + (size_t)gp * DDIM);
    float qs = 0.f;
    #pragma unroll
    for (int d = 0; d < DDIM; d++) {
        float df = zr[d] - cc[d];
        qs += df * df;
    }
    #pragma unroll
    for (int q = 0; q < 32; q++) zq[q] = __ldg(reinterpret_cast<const float4*>(cc) + q);

    __shared__ float red[256];
    red[threadIdx.x] = qs;
    __syncthreads();
    for (int off = 128; off > 0; off >>= 1) {
        if (threadIdx.x < off) red[threadIdx.x] += red[threadIdx.x + off];
        __syncthreads();
    }
    if (threadIdx.x == 0) atomicAdd(&g_acc[0], (double)red[0]);
}

// weight prep: [CO][ci*3+t] fp32 -> K-major [CO][t*CI+ci] bf16 hi/lo
template<int CO, int CI>
__global__ __launch_bounds__(256) void wprep_k(const float* __restrict__ w,
                                               __nv_bfloat16* __restrict__ wh,
                                               __nv_bfloat16* __restrict__ wl) {
    int idx = blockIdx.x * 256 + threadIdx.x;        // over CO*3*CI
    int co = idx / (3 * CI);
    int r  = idx - co * (3 * CI);                    // = t*CI + ci
    int t  = r / CI;
    int ci = r - t * CI;
    float v = w[(size_t)co * 3 * CI + (size_t)ci * 3 + t];
    __nv_bfloat16 h = __float2bfloat16_rn(v);
    wh[idx] = h;
    wl[idx] = __float2bfloat16_rn(v - __bfloat162float(h));
}

// ============ bf16 hi/lo 3-term HMMA conv: CI -> CO, k=3 SAME ============
// CTA tile 128co x 128p; K = 3*CI in chunks of 32; 8 warps (2 m x 4 n),
// warp tile 64co x 32p; mma m16n8k16 bf16.
template<int CI, int CO, bool RELU>
__global__ __launch_bounds__(256, 2) void conv_mma_k(const float* __restrict__ in,
                                                     const __nv_bfloat16* __restrict__ wh,
                                                     const __nv_bfloat16* __restrict__ wl,
                                                     const float* __restrict__ bias,
                                                     float* __restrict__ out) {
    constexpr int KTOT = 3 * CI;
    constexpr int NCH  = KTOT / 32;
    constexpr int RSTR = 80;                 // bytes per smem row (32 bf16 + 16 pad)

    __shared__ __align__(16) char smem_[4 * 128 * RSTR];   // 40 KB
    char* Ah = smem_;
    char* Al = smem_ + 128 * RSTR;
    char* Bh = smem_ + 2 * 128 * RSTR;
    char* Bl = smem_ + 3 * 128 * RSTR;

    const int tid  = threadIdx.x;
    const int lane = tid & 31;
    const int wid  = tid >> 5;
    const int wm   = wid & 1;                // 2 warps over co
    const int wn   = wid >> 1;               // 4 warps over p
    const int g    = lane >> 2;              // group id 0..7
    const int t4   = lane & 3;               // thread-in-group 0..3

    const int bs_base = blockIdx.x * 128;
    const int co_base = blockIdx.y * 128;
    const int s_in_b0 = bs_base & (SLEN - 1);

    float acc[4][4][4];
    #pragma unroll
    for (int i = 0; i < 4; i++)
        #pragma unroll
        for (int j = 0; j < 4; j++)
            #pragma unroll
            for (int e = 0; e < 4; e++) acc[i][j][e] = 0.f;

    for (int kc = 0; kc < NCH; kc++) {
        const int t   = (kc * 32) / CI;       // tap (chunk never crosses taps; CI%32==0)
        const int ci0 = (kc * 32) % CI;
        __syncthreads();

        // ---- A tile: 128co x 32k bf16 (pre-split, coalesced uint4 copies) ----
        #pragma unroll
        for (int j = 0; j < 2; j++) {
            int idx = tid + 256 * j;          // 512 uint4
            int row = idx >> 2, q = idx & 3;
            size_t src = (size_t)(co_base + row) * KTOT + kc * 32;
            uint4 vh = reinterpret_cast<const uint4*>(wh + src)[q];
            uint4 vl = reinterpret_cast<const uint4*>(wl + src)[q];
            *reinterpret_cast<uint4*>(Ah + row * RSTR + q * 16) = vh;
            *reinterpret_cast<uint4*>(Al + row * RSTR + q * 16) = vl;
        }
        // ---- B tile: 128p x 32k (convert fp32 -> hi/lo) ----
        #pragma unroll
        for (int j = 0; j < 4; j++) {
            int idx = tid + 256 * j;          // 1024 float4
            int row = idx >> 3, q = idx & 7;
            int sb = s_in_b0 + row + t - 1;
            float4 v = make_float4(0.f, 0.f, 0.f, 0.f);
            if (sb >= 0 && sb < SLEN)
                v = *reinterpret_cast<const float4*>(
                        in + (size_t)(bs_base + row + t - 1) * CI + ci0 + 4 * q);
            float r0, r1, r2, r3;
            uint32_t hp0 = pack_hi(v.x, v.y, r0, r1);
            uint32_t hp1 = pack_hi(v.z, v.w, r2, r3);
            *reinterpret_cast<uint2*>(Bh + row * RSTR + q * 8) = make_uint2(hp0, hp1);
            *reinterpret_cast<uint2*>(Bl + row * RSTR + q * 8) =
                make_uint2(pack_lo(r0, r1), pack_lo(r2, r3));
        }
        __syncthreads();

        // ---- compute: 2 k16-steps ----
        #pragma unroll
        for (int ks = 0; ks < 2; ks++) {
            const int kb = ks * 32 + t4 * 4;  // byte offset of this thread's k pair
            uint32_t bh[4][2], bl[4][2];
            #pragma unroll
            for (int nf = 0; nf < 4; nf++) {
                int nrow = wn * 32 + nf * 8 + g;
                bh[nf][0] = *reinterpret_cast<uint32_t*>(Bh + nrow * RSTR + kb);
                bh[nf][1] = *reinterpret_cast<uint32_t*>(Bh + nrow * RSTR + kb + 16);
                bl[nf][0] = *reinterpret_cast<uint32_t*>(Bl + nrow * RSTR + kb);
                bl[nf][1] = *reinterpret_cast<uint32_t*>(Bl + nrow * RSTR + kb + 16);
            }
            #pragma unroll
            for (int mf = 0; mf < 4; mf++) {
                int mrow = wm * 64 + mf * 16 + g;
                uint32_t ah[4], al[4];
                ah[0] = *reinterpret_cast<uint32_t*>(Ah + mrow * RSTR + kb);
                ah[1] = *reinterpret_cast<uint32_t*>(Ah + (mrow + 8) * RSTR + kb);
                ah[2] = *reinterpret_cast<uint32_t*>(Ah + mrow * RSTR + kb + 16);
                ah[3] = *reinterpret_cast<uint32_t*>(Ah + (mrow + 8) * RSTR + kb + 16);
                al[0] = *reinterpret_cast<uint32_t*>(Al + mrow * RSTR + kb);
                al[1] = *reinterpret_cast<uint32_t*>(Al + (mrow + 8) * RSTR + kb);
                al[2] = *reinterpret_cast<uint32_t*>(Al + mrow * RSTR + kb + 16);
                al[3] = *reinterpret_cast<uint32_t*>(Al + (mrow + 8) * RSTR + kb + 16);
                #pragma unroll
                for (int nf = 0; nf < 4; nf++) {
                    mma16816(acc[mf][nf], ah, bh[nf]);
                    mma16816(acc[mf][nf], ah, bl[nf]);
                    mma16816(acc[mf][nf], al, bh[nf]);
                }
            }
        }
    }

    // ---- epilogue: bias + lrelu + channel-last store ----
    #pragma unroll
    for (int mf = 0; mf < 4; mf++) {
        int co0 = co_base + wm * 64 + mf * 16 + g;
        float bb0 = bias[co0];
        float bb1 = bias[co0 + 8];
        #pragma unroll
        for (int nf = 0; nf < 4; nf++) {
            int p = bs_base + wn * 32 + nf * 8 + t4 * 2;
            #pragma unroll
            for (int e = 0; e < 2; e++) {
                float v0 = acc[mf][nf][e] + bb0;       // row g,   col t4*2+e
                float v1 = acc[mf][nf][2 + e] + bb1;   // row g+8, col t4*2+e
                if (RELU) {
                    v0 = (v0 >= 0.f) ? v0 : 0.2f * v0;
                    v1 = (v1 >= 0.f) ? v1 : 0.2f * v1;
                }
                out[(size_t)(p + e) * CO + co0]     = v0;
                out[(size_t)(p + e) * CO + co0 + 8] = v1;
            }
        }
    }
}

// ---------------- decoder conv3: H -> 1 (channel-last input) + recon loss ----
__global__ __launch_bounds__(256) void dec3_k(const float* __restrict__ hin,
                                              const float* __restrict__ w,
                                              const float* __restrict__ bias,
                                              const float* __restrict__ x,
                                              float* __restrict__ xrec) {
    __shared__ float ws[HDIM * 3];
    for (int i = threadIdx.x; i < HDIM * 3; i += 256) ws[i] = w[i];
    __syncthreads();

    int wid = threadIdx.x >> 5, lane = threadIdx.x & 31;
    int p = blockIdx.x * 8 + wid;     // global position
    int s = p & (SLEN - 1);

    float acc = 0.f;
    #pragma unroll
    for (int t = 0; t < 3; t++) {
        int sb = s + t - 1;
        if (sb < 0 || sb >= SLEN) continue;
        const float4* r = reinterpret_cast<const float4*>(hin + (size_t)(p + t - 1) * HDIM);
        #pragma unroll
        for (int q = 0; q < 2; q++) {
            float4 v = r[lane * 2 + q];
            int c0 = lane * 8 + q * 4;
            acc += v.x * ws[(c0+0)*3+t] + v.y * ws[(c0+1)*3+t]
                 + v.z * ws[(c0+2)*3+t] + v.w * ws[(c0+3)*3+t];
        }
    }
    #pragma unroll
    for (int off = 16; off > 0; off >>= 1)
        acc += __shfl_xor_sync(0xFFFFFFFFu, acc, off);

    __shared__ float wsum[8];
    if (lane == 0) {
        float a = acc + bias[0];
        xrec[p] = a;
        float diff = x[p] - a;
        wsum[wid] = diff * diff;
    }
    __syncthreads();
    if (threadIdx.x == 0) {
        float s8 = 0.f;
        #pragma unroll
        for (int i = 0; i < 8; i++) s8 += wsum[i];
        atomicAdd(&g_acc[1], (double)s8);
    }
}

// ---------------- finalize losses ----------------
__global__ void fin_k(float* __restrict__ out) {
    double qsum = g_acc[0];
    double rsum = g_acc[1];
    float qm    = (float)(qsum / ((double)BATCH * SLEN * DDIM));
    float recon = (float)(rsum / ((double)BATCH * SLEN));
    float vq    = qm * 0.05f;
    float com   = qm * 0.15f;
    size_t base = (size_t)2 * BATCH * SLEN;
    out[base + 0] = recon + vq + com;
    out[base + 1] = recon;
    out[base + 2] = vq;
    out[base + 3] = com;
}

// ---------------- launch ----------------
extern "C" void kernel_launch(void* const* d_in, const int* in_sizes, int n_in,
                              void* d_out, int out_size) {
    const float* x   = (const float*)d_in[0];
    const float* cb  = (const float*)d_in[1];
    const float* ew1 = (const float*)d_in[2];
    const float* eb1 = (const float*)d_in[3];
    const float* ew2 = (const float*)d_in[4];
    const float* eb2 = (const float*)d_in[5];
    const float* ew3 = (const float*)d_in[6];
    const float* eb3 = (const float*)d_in[7];
    const float* dw1 = (const float*)d_in[8];
    const float* db1 = (const float*)d_in[9];
    const float* dw2 = (const float*)d_in[10];
    const float* db2 = (const float*)d_in[11];
    const float* dw3 = (const float*)d_in[12];
    const float* db3 = (const float*)d_in[13];
    float* out = (float*)d_out;

    float *h1, *h2, *z, *zq, *d1, *d2;
    __nv_bfloat16 *wh, *wl;
    cudaGetSymbolAddress((void**)&h1, g_h1);
    cudaGetSymbolAddress((void**)&h2, g_h2);
    cudaGetSymbolAddress((void**)&z,  g_z);
    cudaGetSymbolAddress((void**)&zq, g_zq);
    cudaGetSymbolAddress((void**)&d1, g_d1);
    cudaGetSymbolAddress((void**)&d2, g_d2);
    cudaGetSymbolAddress((void**)&wh, g_wh);
    cudaGetSymbolAddress((void**)&wl, g_wl);

    init_k<<<1, 32>>>();
    c2_k<<<2, 256>>>(cb);

    // ---------- encoder: proven fp32 SIMT path (channel-first) ----------
    enc1_k<<<(BATCH * HDIM * SLEN) / 256, 256>>>(x, ew1, eb1);

    dim3 g2(SLEN / 64, HDIM / 128, BATCH);
    conv_k<HDIM, HDIM, true><<<g2, 256>>>(h1, ew2, eb2, h2);

    dim3 g3(SLEN / 64, DDIM / 128, BATCH);
    conv_k<HDIM, DDIM, false><<<g3, 256>>>(h2, ew3, eb3, z);

    // ---------- VQ: round-10 proven (bit-exact argmin) ----------
    vq_k<<<(BATCH * SLEN) / 256, 256>>>(cb, out + (size_t)BATCH * SLEN);

    // ---------- decoder: bf16 hi/lo 3-term HMMA ----------
    const int STILES = (BATCH * SLEN) / 128;   // 512

    wprep_k<HDIM, DDIM><<<(HDIM * 3 * DDIM) / 256, 256>>>(dw1, wh, wl);
    conv_mma_k<DDIM, HDIM, true><<<dim3(STILES, HDIM / 128), 256>>>(
        zq, wh, wl, db1, d1);

    wprep_k<HDIM, HDIM><<<(HDIM * 3 * HDIM) / 256, 256>>>(dw2, wh, wl);
    conv_mma_k<HDIM, HDIM, true><<<dim3(STILES, HDIM / 128), 256>>>(
        d1, wh, wl, db2, d2);

    dec3_k<<<(BATCH * SLEN) / 8, 256>>>(d2, dw3, db3, x, out);

    fin_k<<<1, 1>>>(out);
}